// round 9
// baseline (speedup 1.0000x reference)
#include <cuda_runtime.h>
#include <cuda_bf16.h>
#include <math.h>
#include <stdint.h>

#define T_DIM 512
#define B_DIM 64
#define IC 512
#define HC 512
#define L_DIM 2
#define K1 1024      // IC + HC (weight row stride)
#define N1 1024      // 2 * HC
#define NB 128       // serial CTAs: 8 groups x 16
#define NT 512       // serial threads per block (16 warps)
#define NGRP 8
#define GSZ 16       // CTAs per group

#define M_ALL (T_DIM * B_DIM)          // 32768
#define N_ALL (N1 + HC)                // 1536

#define OUT_ACT ((size_t)T_DIM * B_DIM * HC)

// ---------------- device-global scratch (allocation-free rule) ----------------
__device__ float g_act [(size_t)T_DIM * B_DIM * HC];
__device__ float g_pre1[(size_t)T_DIM * B_DIM * N1];
__device__ float g_pre2[(size_t)T_DIM * B_DIM * HC];
__device__ float g_h [B_DIM * HC];
__device__ float g_rh[B_DIM * HC];
__device__ float g_z [B_DIM * HC];
__device__ __nv_bfloat16 g_ahi[(size_t)M_ALL * IC];
__device__ __nv_bfloat16 g_alo[(size_t)M_ALL * IC];
__device__ __nv_bfloat16 g_whi[(size_t)N_ALL * IC];
__device__ __nv_bfloat16 g_wlo[(size_t)N_ALL * IC];
__device__ unsigned g_gcnt[NGRP * 32];   // one 128B line per group
__device__ unsigned g_ggen[NGRP * 32];
__device__ unsigned g_dead = 0;

__device__ __forceinline__ unsigned ld_u32_cg(const unsigned* p) {
    unsigned v;
    asm volatile("ld.global.cg.u32 %0, [%1];" : "=r"(v) : "l"(p) : "memory");
    return v;
}

// Group barrier (16 arrivals): atomic arrivals, epoch release, plain-load
// pollers, bounded spin -> terminating wrong answer, never a wedged device.
__device__ __forceinline__ void group_bar(int g, unsigned target) {
    __syncthreads();
    if (threadIdx.x == 0) {
        if (ld_u32_cg(&g_dead) == 0u) {
            __threadfence();
            unsigned t = atomicAdd(&g_gcnt[g * 32], 1u);
            if (t == GSZ - 1) {
                g_gcnt[g * 32] = 0;
                __threadfence();
                atomicExch(&g_ggen[g * 32], target);
            } else {
                int it = 0;
                while (ld_u32_cg(&g_ggen[g * 32]) != target) {
                    if (++it > (1 << 20)) { atomicExch(&g_dead, 1u); break; }
                }
            }
            __threadfence();
        }
    }
    __syncthreads();
}

// =====================================================================
// Split-conversion kernels: fp32 -> (bf16 hi, bf16 lo), lo = v - hi.
// =====================================================================
__device__ __forceinline__ void split4(float4 v, uint2& hi, uint2& lo) {
    __nv_bfloat16 h0 = __float2bfloat16_rn(v.x);
    __nv_bfloat16 h1 = __float2bfloat16_rn(v.y);
    __nv_bfloat16 h2 = __float2bfloat16_rn(v.z);
    __nv_bfloat16 h3 = __float2bfloat16_rn(v.w);
    __nv_bfloat16 l0 = __float2bfloat16_rn(v.x - __bfloat162float(h0));
    __nv_bfloat16 l1 = __float2bfloat16_rn(v.y - __bfloat162float(h1));
    __nv_bfloat16 l2 = __float2bfloat16_rn(v.z - __bfloat162float(h2));
    __nv_bfloat16 l3 = __float2bfloat16_rn(v.w - __bfloat162float(h3));
    hi.x = (unsigned)__bfloat16_as_ushort(h0) | ((unsigned)__bfloat16_as_ushort(h1) << 16);
    hi.y = (unsigned)__bfloat16_as_ushort(h2) | ((unsigned)__bfloat16_as_ushort(h3) << 16);
    lo.x = (unsigned)__bfloat16_as_ushort(l0) | ((unsigned)__bfloat16_as_ushort(l1) << 16);
    lo.y = (unsigned)__bfloat16_as_ushort(l2) | ((unsigned)__bfloat16_as_ushort(l3) << 16);
}

__global__ void __launch_bounds__(256)
conv_act(const float* __restrict__ x, int l)
{
    const float* lin = (l == 0) ? x : g_act;
    size_t i = (size_t)blockIdx.x * 256 + threadIdx.x;
    float4 v = ((const float4*)lin)[i];
    uint2 hi, lo;
    split4(v, hi, lo);
    ((uint2*)g_ahi)[i] = hi;
    ((uint2*)g_alo)[i] = lo;
}

__global__ void __launch_bounds__(256)
conv_w(const float* __restrict__ W1, const float* __restrict__ W2, int l)
{
    size_t i = (size_t)blockIdx.x * 256 + threadIdx.x;
    int n  = (int)(i >> 7);
    int k4 = (int)(i & 127);
    const float* src = (n < N1)
        ? (W1 + (size_t)l * N1 * K1 + (size_t)n * K1 + k4 * 4)
        : (W2 + (size_t)l * HC * K1 + (size_t)(n - N1) * K1 + k4 * 4);
    float4 v = *(const float4*)src;
    uint2 hi, lo;
    split4(v, hi, lo);
    ((uint2*)g_whi)[(size_t)n * 128 + k4] = hi;
    ((uint2*)g_wlo)[(size_t)n * 128 + k4] = lo;
}

// =====================================================================
// mma hoist (unchanged from round 8): bf16 two-term split tensor GEMM.
// =====================================================================
#define MBM 128
#define MBN 64
#define MBK 32
#define SAPAD 40

__device__ __forceinline__ void mma16816(float* c, const unsigned* a, const unsigned* b) {
    asm volatile(
        "mma.sync.aligned.m16n8k16.row.col.f32.bf16.bf16.f32 "
        "{%0,%1,%2,%3}, {%4,%5,%6,%7}, {%8,%9}, {%0,%1,%2,%3};\n"
        : "+f"(c[0]), "+f"(c[1]), "+f"(c[2]), "+f"(c[3])
        : "r"(a[0]), "r"(a[1]), "r"(a[2]), "r"(a[3]), "r"(b[0]), "r"(b[1]));
}

__global__ void __launch_bounds__(256)
mma_hoist(const float* __restrict__ b1, const float* __restrict__ b2, int l)
{
    __shared__ __nv_bfloat16 sA[2][MBM][SAPAD];
    __shared__ __nv_bfloat16 sB[2][MBN][SAPAD];

    const int bn  = blockIdx.x;
    const int m0  = blockIdx.y * MBM;
    const int tid = threadIdx.x;
    const int wid = tid >> 5, lane = tid & 31;
    const int wm  = wid & 3;
    const int wn  = wid >> 2;

    float* outp;  const float* bp;  int nstr, n0, wrow0;
    if (bn < 16) { n0 = bn * MBN;        wrow0 = n0;       outp = g_pre1; nstr = N1; bp = b1 + l * N1 + n0; }
    else         { n0 = (bn - 16) * MBN; wrow0 = N1 + n0;  outp = g_pre2; nstr = HC; bp = b2 + l * HC + n0; }

    const __nv_bfloat16* segA[3] = { g_ahi, g_ahi, g_alo };
    const __nv_bfloat16* segW[3] = { g_whi, g_wlo, g_whi };

    const int ar = tid >> 2;
    const int aq = (tid & 3) * 8;

    float acc[2][4][4];
    #pragma unroll
    for (int mt = 0; mt < 2; ++mt)
        #pragma unroll
        for (int nt = 0; nt < 4; ++nt)
            #pragma unroll
            for (int q = 0; q < 4; ++q) acc[mt][nt][q] = 0.f;

    {
        const __nv_bfloat16* A = segA[0];
        const __nv_bfloat16* W = segW[0];
        uint4 a0 = *(const uint4*)(A + (size_t)(m0 + ar) * IC + aq);
        uint4 a1 = *(const uint4*)(A + (size_t)(m0 + ar + 64) * IC + aq);
        uint4 w0 = *(const uint4*)(W + (size_t)(wrow0 + ar) * IC + aq);
        *(uint4*)&sA[0][ar][aq]      = a0;
        *(uint4*)&sA[0][ar + 64][aq] = a1;
        *(uint4*)&sB[0][ar][aq]      = w0;
    }
    __syncthreads();

    const int NIT = 48;
    for (int it = 0; it < NIT; ++it) {
        const int cur = it & 1;
        const bool more = (it + 1) < NIT;
        uint4 na0, na1, nw0;
        if (more) {
            int seg = (it + 1) >> 4;
            int kt  = ((it + 1) & 15) * MBK;
            const __nv_bfloat16* A = segA[seg];
            const __nv_bfloat16* W = segW[seg];
            na0 = *(const uint4*)(A + (size_t)(m0 + ar) * IC + kt + aq);
            na1 = *(const uint4*)(A + (size_t)(m0 + ar + 64) * IC + kt + aq);
            nw0 = *(const uint4*)(W + (size_t)(wrow0 + ar) * IC + kt + aq);
        }

        #pragma unroll
        for (int ks = 0; ks < MBK; ks += 16) {
            const int kb = ks + (lane & 3) * 2;
            unsigned af[2][4], bf[4][2];
            #pragma unroll
            for (int mt = 0; mt < 2; ++mt) {
                int r = wm * 32 + mt * 16 + (lane >> 2);
                af[mt][0] = *(const unsigned*)&sA[cur][r][kb];
                af[mt][1] = *(const unsigned*)&sA[cur][r + 8][kb];
                af[mt][2] = *(const unsigned*)&sA[cur][r][kb + 8];
                af[mt][3] = *(const unsigned*)&sA[cur][r + 8][kb + 8];
            }
            #pragma unroll
            for (int nt = 0; nt < 4; ++nt) {
                int c = wn * 32 + nt * 8 + (lane >> 2);
                bf[nt][0] = *(const unsigned*)&sB[cur][c][kb];
                bf[nt][1] = *(const unsigned*)&sB[cur][c][kb + 8];
            }
            #pragma unroll
            for (int mt = 0; mt < 2; ++mt)
                #pragma unroll
                for (int nt = 0; nt < 4; ++nt)
                    mma16816(acc[mt][nt], af[mt], bf[nt]);
        }

        if (more) {
            const int nxt = cur ^ 1;
            *(uint4*)&sA[nxt][ar][aq]      = na0;
            *(uint4*)&sA[nxt][ar + 64][aq] = na1;
            *(uint4*)&sB[nxt][ar][aq]      = nw0;
            __syncthreads();
        }
    }

    #pragma unroll
    for (int mt = 0; mt < 2; ++mt) {
        #pragma unroll
        for (int nt = 0; nt < 4; ++nt) {
            int r  = m0 + wm * 32 + mt * 16 + (lane >> 2);
            int cl = wn * 32 + nt * 8 + (lane & 3) * 2;
            float bx = bp[cl], by = bp[cl + 1];
            float2 o0 = { acc[mt][nt][0] + bx, acc[mt][nt][1] + by };
            float2 o1 = { acc[mt][nt][2] + bx, acc[mt][nt][3] + by };
            *(float2*)(outp + (size_t)r * nstr + n0 + cl)       = o0;
            *(float2*)(outp + (size_t)(r + 8) * nstr + n0 + cl) = o1;
        }
    }
}

// =====================================================================
// Serial kernel, group-partitioned: 8 groups x 16 CTAs; group g owns
// batches [g*8, g*8+8). CTA i of a group owns phase-1 j-slice
// [i*64,+64) (ws1: 64x512 = 128KB) and phase-2 j-slice [i*32,+32)
// (ws2: 32x512 = 64KB). Sync = 16-arrival group barrier.
// Warp layout: phase1 w=(jh,ks): lane=j, 8 k-splits of 64, all 8 b per
// warp; phase2 w=ks (16 splits of 32), lane=j, all 8 b.
// smem: ws1 128K | ws2 64K | hs 16K | red 16K = 224KB
// =====================================================================
#define SER_SMEM_FLOATS (32768 + 16384 + 4096 + 4096)
#define SER_SMEM_BYTES  (SER_SMEM_FLOATS * 4)

__global__ void __launch_bounds__(NT, 1)
serial_kernel(const float* __restrict__ hiddens,
              const float* __restrict__ W1, const float* __restrict__ W2,
              float* __restrict__ out, int l)
{
    extern __shared__ float sm[];
    float* ws1 = sm;                  // [k4 128][j 64][kk 4]
    float* ws2 = sm + 32768;          // [k4 128][j 32][kk 4]
    float* hs  = sm + 49152;          // [b 8][k 512] (h, then rh)
    float* red = sm + 53248;          // [w 16][b 8][lane 32]

    const int tid  = threadIdx.x;
    const int bid  = blockIdx.x;
    const int w    = tid >> 5;
    const int lane = tid & 31;
    const int g    = bid >> 4;        // group 0..7
    const int ci   = bid & 15;        // rank in group 0..15

    float* lout = (l == 0) ? g_act : out;

    // Per-thread output coords
    const int jl1 = tid & 63, bl1 = tid >> 6;          // phase1: 64j x 8b
    const int j1g = ci * 64 + jl1;                     // 0..1023 gate index
    const int b1g = g * 8 + bl1;
    const int jl2 = tid & 31, bl2 = (tid >> 5) & 7;    // phase2: 32j x 8b
    const int j2g = ci * 32 + jl2;
    const int b2g = g * 8 + bl2;
    const bool p2own = (tid < 256);

    // Stage transposed h-part weights once per layer
    for (int idx = tid; idx < 64 * 512; idx += NT) {
        int jl = idx >> 9, k = idx & 511;
        ws1[(k >> 2) * 256 + jl * 4 + (k & 3)] =
            W1[((size_t)l * N1 + ci * 64 + jl) * K1 + IC + k];
    }
    for (int idx = tid; idx < 32 * 512; idx += NT) {
        int jl = idx >> 9, k = idx & 511;
        ws2[(k >> 2) * 128 + jl * 4 + (k & 3)] =
            W2[((size_t)l * HC + ci * 32 + jl) * K1 + IC + k];
    }

    // Init hidden state for THIS group's 8 batches (group-local coverage):
    // 16 CTAs x 512 threads = 8192 slots for 4096 values.
    {
        int idx = ci * NT + tid;
        if (idx < 8 * HC) {
            int bl = idx >> 9, k = idx & 511;
            g_h[(g * 8 + bl) * HC + k] = hiddens[l * HC + k];
        }
    }

    unsigned ep = ld_u32_cg(&g_ggen[g * 32]);
    group_bar(g, ++ep);

    const float4* gh4  = (const float4*)g_h;
    const float4* grh4 = (const float4*)g_rh;
    float4* hsv = (float4*)hs;
    const float4* ws1v = (const float4*)ws1;
    const float4* ws2v = (const float4*)ws2;

    for (int t = 0; t < T_DIM; ++t) {
        // ---- stage hs = h[g*8..+8][:] (1024 float4); prefetch t-only operands
        #pragma unroll
        for (int q = 0; q < 2; ++q) {
            int idx = q * NT + tid;
            hsv[idx] = __ldcg(&gh4[(size_t)g * 1024 + idx]);
        }
        float pre1v = __ldcg(&g_pre1[((size_t)t * B_DIM + b1g) * N1 + j1g]);
        float pre2v = 0.f, hov = 0.f;
        if (p2own) {
            pre2v = __ldcg(&g_pre2[((size_t)t * B_DIM + b2g) * HC + j2g]);
            hov   = __ldcg(&g_h[b2g * HC + j2g]);
        }
        __syncthreads();

        // ---- Phase 1 compute: h @ W1h^T, warp covers 32j x 64k x 8b ----
        {
            const int jh = w & 1;          // j half
            const int ks = w >> 1;         // k split 0..7
            const int jloc = jh * 32 + lane;
            float acc[8];
            #pragma unroll
            for (int b = 0; b < 8; ++b) acc[b] = 0.f;
            const float4* wq = ws1v + (size_t)(ks * 16) * 64 + jloc;
            const float4* xb = hsv + ks * 16;
            #pragma unroll 4
            for (int k4 = 0; k4 < 16; ++k4) {
                float4 wv = wq[(size_t)k4 * 64];
                #pragma unroll
                for (int b = 0; b < 8; ++b) {
                    float4 xv = xb[b * 128 + k4];
                    acc[b] = fmaf(wv.x, xv.x, acc[b]);
                    acc[b] = fmaf(wv.y, xv.y, acc[b]);
                    acc[b] = fmaf(wv.z, xv.z, acc[b]);
                    acc[b] = fmaf(wv.w, xv.w, acc[b]);
                }
            }
            #pragma unroll
            for (int b = 0; b < 8; ++b)
                red[w * 256 + b * 32 + lane] = acc[b];
        }
        __syncthreads();

        // ---- Phase 1 epilogue: 1 output/thread (64j x 8b) ----
        {
            const int jh = jl1 >> 5, ln = jl1 & 31;
            float s = 0.f;
            #pragma unroll
            for (int ks = 0; ks < 8; ++ks)
                s += red[(ks * 2 + jh) * 256 + bl1 * 32 + ln];
            float pre = s + pre1v;
            float sg  = __fdividef(1.f, 1.f + __expf(-pre));
            if (j1g < HC) {                       // r gate -> r*h
                float hv = hs[bl1 * 512 + j1g];   // h from smem stage
                g_rh[b1g * HC + j1g] = sg * hv;
            } else {                              // z gate
                g_z[b1g * HC + (j1g - HC)] = sg;
            }
        }
        group_bar(g, ++ep);

        // ---- stage hs = rh[g*8..+8][:]; prefetch z ----
        #pragma unroll
        for (int q = 0; q < 2; ++q) {
            int idx = q * NT + tid;
            hsv[idx] = __ldcg(&grh4[(size_t)g * 1024 + idx]);
        }
        float zv = 0.f;
        if (p2own) zv = __ldcg(&g_z[b2g * HC + j2g]);
        __syncthreads();

        // ---- Phase 2 compute: rh @ W2h^T, warp covers 32j x 32k x 8b ----
        {
            const int ks = w;              // 0..15
            float acc[8];
            #pragma unroll
            for (int b = 0; b < 8; ++b) acc[b] = 0.f;
            const float4* wq = ws2v + (size_t)(ks * 8) * 32 + lane;
            const float4* xb = hsv + ks * 8;
            #pragma unroll 4
            for (int k4 = 0; k4 < 8; ++k4) {
                float4 wv = wq[(size_t)k4 * 32];
                #pragma unroll
                for (int b = 0; b < 8; ++b) {
                    float4 xv = xb[b * 128 + k4];
                    acc[b] = fmaf(wv.x, xv.x, acc[b]);
                    acc[b] = fmaf(wv.y, xv.y, acc[b]);
                    acc[b] = fmaf(wv.z, xv.z, acc[b]);
                    acc[b] = fmaf(wv.w, xv.w, acc[b]);
                }
            }
            #pragma unroll
            for (int b = 0; b < 8; ++b)
                red[w * 256 + b * 32 + lane] = acc[b];
        }
        __syncthreads();

        // ---- Phase 2 epilogue: threads 0..255 (32j x 8b) ----
        if (p2own) {
            float s = 0.f;
            #pragma unroll
            for (int ks = 0; ks < 16; ++ks)
                s += red[ks * 256 + bl2 * 32 + jl2];
            float x2v = s + pre2v;
            float gg  = 1.f - __fdividef(2.f, __expf(2.f * x2v) + 1.f);
            float hn  = zv * hov + (1.f - zv) * gg;
            g_h[b2g * HC + j2g] = hn;
            lout[((size_t)t * B_DIM + b2g) * HC + j2g] = hn;
            if (t == T_DIM - 1)
                out[OUT_ACT + (size_t)l * B_DIM * HC + b2g * HC + j2g] = hn;
        }
        group_bar(g, ++ep);
    }
}

extern "C" void kernel_launch(void* const* d_in, const int* in_sizes, int n_in,
                              void* d_out, int out_size) {
    const float* x       = (const float*)d_in[0];
    const float* hiddens = (const float*)d_in[1];
    const float* W1      = (const float*)d_in[2];
    const float* b1      = (const float*)d_in[3];
    const float* W2      = (const float*)d_in[4];
    const float* b2      = (const float*)d_in[5];
    float* out = (float*)d_out;

    cudaFuncSetAttribute(serial_kernel,
                         cudaFuncAttributeMaxDynamicSharedMemorySize,
                         SER_SMEM_BYTES);

    for (int l = 0; l < L_DIM; ++l) {
        conv_act<<<M_ALL * IC / 4 / 256, 256>>>(x, l);
        conv_w  <<<N_ALL * IC / 4 / 256, 256>>>(W1, W2, l);
        mma_hoist<<<dim3(24, M_ALL / MBM), 256>>>(b1, b2, l);
        serial_kernel<<<NB, NT, SER_SMEM_BYTES>>>(hiddens, W1, W2, out, l);
    }
}

// round 10
// speedup vs baseline: 1.7545x; 1.7545x over previous
#include <cuda_runtime.h>
#include <cuda_bf16.h>
#include <math.h>
#include <stdint.h>

#define T_DIM 512
#define B_DIM 64
#define IC 512
#define HC 512
#define L_DIM 2
#define K1 1024      // IC + HC (weight row stride)
#define N1 1024      // 2 * HC
#define NB 128       // serial blocks (1 CTA/SM, co-resident)
#define NT 512       // serial threads per block (16 warps)

#define M_ALL (T_DIM * B_DIM)          // 32768
#define N_ALL (N1 + HC)                // 1536

#define OUT_ACT ((size_t)T_DIM * B_DIM * HC)

// ---------------- device-global scratch (allocation-free rule) ----------------
__device__ float g_act [(size_t)T_DIM * B_DIM * HC];
__device__ float g_pre1[(size_t)T_DIM * B_DIM * N1];
__device__ float g_pre2[(size_t)T_DIM * B_DIM * HC];
__device__ float g_h [B_DIM * HC];
__device__ float g_rh[B_DIM * HC];
__device__ float g_z [B_DIM * HC];
__device__ __nv_bfloat16 g_ahi[(size_t)M_ALL * IC];
__device__ __nv_bfloat16 g_alo[(size_t)M_ALL * IC];
__device__ __nv_bfloat16 g_whi[(size_t)N_ALL * IC];
__device__ __nv_bfloat16 g_wlo[(size_t)N_ALL * IC];
__device__ unsigned g_bar_cnt = 0;
__device__ unsigned g_bar_gen = 0;
__device__ unsigned g_dead    = 0;

__device__ __forceinline__ unsigned ld_u32_cg(const unsigned* p) {
    unsigned v;
    asm volatile("ld.global.cg.u32 %0, [%1];" : "=r"(v) : "l"(p) : "memory");
    return v;
}

// Grid barrier (round-8 proven): atomic arrivals, epoch release, plain-load
// pollers, bounded spin -> terminating wrong answer, never a wedged device.
__device__ __forceinline__ void grid_bar(unsigned target) {
    __syncthreads();
    if (threadIdx.x == 0) {
        if (ld_u32_cg(&g_dead) == 0u) {
            __threadfence();
            unsigned t = atomicAdd(&g_bar_cnt, 1u);
            if (t == NB - 1) {
                g_bar_cnt = 0;
                __threadfence();
                atomicExch(&g_bar_gen, target);
            } else {
                int it = 0;
                while (ld_u32_cg(&g_bar_gen) != target) {
                    if (++it > (1 << 20)) { atomicExch(&g_dead, 1u); break; }
                }
            }
            __threadfence();
        }
    }
    __syncthreads();
}

// ---------------- fp32 -> (bf16 hi, bf16 lo) split ----------------
__device__ __forceinline__ void split4(float4 v, uint2& hi, uint2& lo) {
    __nv_bfloat16 h0 = __float2bfloat16_rn(v.x);
    __nv_bfloat16 h1 = __float2bfloat16_rn(v.y);
    __nv_bfloat16 h2 = __float2bfloat16_rn(v.z);
    __nv_bfloat16 h3 = __float2bfloat16_rn(v.w);
    __nv_bfloat16 l0 = __float2bfloat16_rn(v.x - __bfloat162float(h0));
    __nv_bfloat16 l1 = __float2bfloat16_rn(v.y - __bfloat162float(h1));
    __nv_bfloat16 l2 = __float2bfloat16_rn(v.z - __bfloat162float(h2));
    __nv_bfloat16 l3 = __float2bfloat16_rn(v.w - __bfloat162float(h3));
    hi.x = (unsigned)__bfloat16_as_ushort(h0) | ((unsigned)__bfloat16_as_ushort(h1) << 16);
    hi.y = (unsigned)__bfloat16_as_ushort(h2) | ((unsigned)__bfloat16_as_ushort(h3) << 16);
    lo.x = (unsigned)__bfloat16_as_ushort(l0) | ((unsigned)__bfloat16_as_ushort(l1) << 16);
    lo.y = (unsigned)__bfloat16_as_ushort(l2) | ((unsigned)__bfloat16_as_ushort(l3) << 16);
}

__global__ void __launch_bounds__(256)
conv_act(const float* __restrict__ x, int l)
{
    const float* lin = (l == 0) ? x : g_act;
    size_t i = (size_t)blockIdx.x * 256 + threadIdx.x;
    float4 v = ((const float4*)lin)[i];
    uint2 hi, lo;
    split4(v, hi, lo);
    ((uint2*)g_ahi)[i] = hi;
    ((uint2*)g_alo)[i] = lo;
}

__global__ void __launch_bounds__(256)
conv_w(const float* __restrict__ W1, const float* __restrict__ W2, int l)
{
    size_t i = (size_t)blockIdx.x * 256 + threadIdx.x;
    int n  = (int)(i >> 7);
    int k4 = (int)(i & 127);
    const float* src = (n < N1)
        ? (W1 + (size_t)l * N1 * K1 + (size_t)n * K1 + k4 * 4)
        : (W2 + (size_t)l * HC * K1 + (size_t)(n - N1) * K1 + k4 * 4);
    float4 v = *(const float4*)src;
    uint2 hi, lo;
    split4(v, hi, lo);
    ((uint2*)g_whi)[(size_t)n * 128 + k4] = hi;
    ((uint2*)g_wlo)[(size_t)n * 128 + k4] = lo;
}

// =====================================================================
// mma hoist (unchanged, proven): bf16 two-term split tensor GEMM.
// =====================================================================
#define MBM 128
#define MBN 64
#define MBK 32
#define SAPAD 40

__device__ __forceinline__ void mma16816(float* c, const unsigned* a, const unsigned* b) {
    asm volatile(
        "mma.sync.aligned.m16n8k16.row.col.f32.bf16.bf16.f32 "
        "{%0,%1,%2,%3}, {%4,%5,%6,%7}, {%8,%9}, {%0,%1,%2,%3};\n"
        : "+f"(c[0]), "+f"(c[1]), "+f"(c[2]), "+f"(c[3])
        : "r"(a[0]), "r"(a[1]), "r"(a[2]), "r"(a[3]), "r"(b[0]), "r"(b[1]));
}

__global__ void __launch_bounds__(256)
mma_hoist(const float* __restrict__ b1, const float* __restrict__ b2, int l)
{
    __shared__ __nv_bfloat16 sA[2][MBM][SAPAD];
    __shared__ __nv_bfloat16 sB[2][MBN][SAPAD];

    const int bn  = blockIdx.x;
    const int m0  = blockIdx.y * MBM;
    const int tid = threadIdx.x;
    const int wid = tid >> 5, lane = tid & 31;
    const int wm  = wid & 3;
    const int wn  = wid >> 2;

    float* outp;  const float* bp;  int nstr, n0, wrow0;
    if (bn < 16) { n0 = bn * MBN;        wrow0 = n0;       outp = g_pre1; nstr = N1; bp = b1 + l * N1 + n0; }
    else         { n0 = (bn - 16) * MBN; wrow0 = N1 + n0;  outp = g_pre2; nstr = HC; bp = b2 + l * HC + n0; }

    const __nv_bfloat16* segA[3] = { g_ahi, g_ahi, g_alo };
    const __nv_bfloat16* segW[3] = { g_whi, g_wlo, g_whi };

    const int ar = tid >> 2;
    const int aq = (tid & 3) * 8;

    float acc[2][4][4];
    #pragma unroll
    for (int mt = 0; mt < 2; ++mt)
        #pragma unroll
        for (int nt = 0; nt < 4; ++nt)
            #pragma unroll
            for (int q = 0; q < 4; ++q) acc[mt][nt][q] = 0.f;

    {
        const __nv_bfloat16* A = segA[0];
        const __nv_bfloat16* W = segW[0];
        uint4 a0 = *(const uint4*)(A + (size_t)(m0 + ar) * IC + aq);
        uint4 a1 = *(const uint4*)(A + (size_t)(m0 + ar + 64) * IC + aq);
        uint4 w0 = *(const uint4*)(W + (size_t)(wrow0 + ar) * IC + aq);
        *(uint4*)&sA[0][ar][aq]      = a0;
        *(uint4*)&sA[0][ar + 64][aq] = a1;
        *(uint4*)&sB[0][ar][aq]      = w0;
    }
    __syncthreads();

    const int NIT = 48;
    for (int it = 0; it < NIT; ++it) {
        const int cur = it & 1;
        const bool more = (it + 1) < NIT;
        uint4 na0, na1, nw0;
        if (more) {
            int seg = (it + 1) >> 4;
            int kt  = ((it + 1) & 15) * MBK;
            const __nv_bfloat16* A = segA[seg];
            const __nv_bfloat16* W = segW[seg];
            na0 = *(const uint4*)(A + (size_t)(m0 + ar) * IC + kt + aq);
            na1 = *(const uint4*)(A + (size_t)(m0 + ar + 64) * IC + kt + aq);
            nw0 = *(const uint4*)(W + (size_t)(wrow0 + ar) * IC + kt + aq);
        }

        #pragma unroll
        for (int ks = 0; ks < MBK; ks += 16) {
            const int kb = ks + (lane & 3) * 2;
            unsigned af[2][4], bf[4][2];
            #pragma unroll
            for (int mt = 0; mt < 2; ++mt) {
                int r = wm * 32 + mt * 16 + (lane >> 2);
                af[mt][0] = *(const unsigned*)&sA[cur][r][kb];
                af[mt][1] = *(const unsigned*)&sA[cur][r + 8][kb];
                af[mt][2] = *(const unsigned*)&sA[cur][r][kb + 8];
                af[mt][3] = *(const unsigned*)&sA[cur][r + 8][kb + 8];
            }
            #pragma unroll
            for (int nt = 0; nt < 4; ++nt) {
                int c = wn * 32 + nt * 8 + (lane >> 2);
                bf[nt][0] = *(const unsigned*)&sB[cur][c][kb];
                bf[nt][1] = *(const unsigned*)&sB[cur][c][kb + 8];
            }
            #pragma unroll
            for (int mt = 0; mt < 2; ++mt)
                #pragma unroll
                for (int nt = 0; nt < 4; ++nt)
                    mma16816(acc[mt][nt], af[mt], bf[nt]);
        }

        if (more) {
            const int nxt = cur ^ 1;
            *(uint4*)&sA[nxt][ar][aq]      = na0;
            *(uint4*)&sA[nxt][ar + 64][aq] = na1;
            *(uint4*)&sB[nxt][ar][aq]      = nw0;
            __syncthreads();
        }
    }

    #pragma unroll
    for (int mt = 0; mt < 2; ++mt) {
        #pragma unroll
        for (int nt = 0; nt < 4; ++nt) {
            int r  = m0 + wm * 32 + mt * 16 + (lane >> 2);
            int cl = wn * 32 + nt * 8 + (lane & 3) * 2;
            float bx = bp[cl], by = bp[cl + 1];
            float2 o0 = { acc[mt][nt][0] + bx, acc[mt][nt][1] + by };
            float2 o1 = { acc[mt][nt][2] + bx, acc[mt][nt][3] + by };
            *(float2*)(outp + (size_t)r * nstr + n0 + cl)       = o0;
            *(float2*)(outp + (size_t)(r + 8) * nstr + n0 + cl) = o1;
        }
    }
}

// =====================================================================
// Serial kernel: round-8 skeleton (partitioning, barrier, staging,
// epilogue semantics) with phase GEMMs moved to bf16-split tensor cores.
//   Phase 1: CTA = 32 j (jg1=bid>>2) x 16 b (bg1=bid&3). m16n32k512.
//   Phase 2: CTA = 32 j (jg2=bid>>3) x  8 b (bg2=bid&7). m16(8 valid)n32k512.
//   Warp (16): ks = w>>1 (64 k), jp = w&1 (2 j-tiles of 8). K-split
//   partials reduced in fp32 smem.
// smem bytes: W1 hi/lo 2x33280 | W2 hi/lo 2x33280 | H hi/lo 2x16640 |
//             red 16384  = 182784
// =====================================================================
#define WS 520      // smem row stride in halfs (bank-conflict-free frags)
#define OFF_W1H 0
#define OFF_W1L 33280
#define OFF_W2H 66560
#define OFF_W2L 99840
#define OFF_HH  133120
#define OFF_HL  149760
#define OFF_RED 166400
#define SER_SMEM_BYTES 182784

__global__ void __launch_bounds__(NT, 1)
serial_kernel(const float* __restrict__ hiddens,
              const float* __restrict__ W1, const float* __restrict__ W2,
              float* __restrict__ out, int l)
{
    extern __shared__ char smc[];
    __nv_bfloat16* sW1h = (__nv_bfloat16*)(smc + OFF_W1H);
    __nv_bfloat16* sW1l = (__nv_bfloat16*)(smc + OFF_W1L);
    __nv_bfloat16* sW2h = (__nv_bfloat16*)(smc + OFF_W2H);
    __nv_bfloat16* sW2l = (__nv_bfloat16*)(smc + OFF_W2L);
    __nv_bfloat16* sHh  = (__nv_bfloat16*)(smc + OFF_HH);
    __nv_bfloat16* sHl  = (__nv_bfloat16*)(smc + OFF_HL);
    float*         red  = (float*)(smc + OFF_RED);   // [ks 8][jt 4][lane 32][4]

    const int tid  = threadIdx.x;
    const int bid  = blockIdx.x;
    const int wp   = tid >> 5;
    const int lane = tid & 31;

    const int jg1 = bid >> 2;   // 0..31
    const int bg1 = bid & 3;    // 0..3
    const int jg2 = bid >> 3;   // 0..15
    const int bg2 = bid & 7;    // 0..7

    float* lout = (l == 0) ? g_act : out;

    // Per-thread output coords (round-8 semantics)
    const int jl1 = tid & 31, bl1 = tid >> 5;           // phase1: 32j x 16b
    const int j1  = jg1 * 32 + jl1;
    const int b1o = bg1 * 16 + bl1;
    const int jl2 = tid & 31, bl2 = (tid >> 5) & 7;     // phase2: 32j x 8b
    const int j2  = jg2 * 32 + jl2;
    const int b2o = bg2 * 8 + bl2;
    const bool p2own = (tid < 256);

    // Fragment coords for epilogue reads
    const int lf1 = (bl1 & 7) * 4 + ((jl1 & 7) >> 1);
    const int cc1 = (jl1 & 1) + ((bl1 >> 3) << 1);
    const int jt1 = jl1 >> 3;
    const int lf2 = bl2 * 4 + ((jl2 & 7) >> 1);
    const int cc2 = jl2 & 1;
    const int jt2 = jl2 >> 3;

    // ---- stage bf16-split weights once per layer ----
    for (int idx = tid; idx < 32 * 128; idx += NT) {    // idx over float4
        int jl = idx >> 7, k4 = idx & 127;
        float4 v1 = *(const float4*)&W1[((size_t)l * N1 + jg1 * 32 + jl) * K1 + IC + k4 * 4];
        float4 v2 = *(const float4*)&W2[((size_t)l * HC + jg2 * 32 + jl) * K1 + IC + k4 * 4];
        uint2 hi, lo;
        split4(v1, hi, lo);
        *(uint2*)&sW1h[jl * WS + k4 * 4] = hi;
        *(uint2*)&sW1l[jl * WS + k4 * 4] = lo;
        split4(v2, hi, lo);
        *(uint2*)&sW2h[jl * WS + k4 * 4] = hi;
        *(uint2*)&sW2l[jl * WS + k4 * 4] = lo;
    }

    // Init hidden state
    { int i = bid * NT + tid;
      if (i < B_DIM * HC) g_h[i] = hiddens[l * HC + (i & (HC - 1))]; }

    unsigned ep = ld_u32_cg(&g_bar_gen);
    grid_bar(++ep);

    const float4* gh4  = (const float4*)g_h;
    const float4* grh4 = (const float4*)g_rh;

    const int frow = lane >> 2;          // fragment row 0..7
    const int fkq  = (lane & 3) * 2;     // fragment k offset

    for (int t = 0; t < T_DIM; ++t) {
        // ---- prefetch t-only operands (recurrence-ready after last barrier)
        float pre1v = __ldcg(&g_pre1[((size_t)t * B_DIM + b1o) * N1 + j1]);
        float hv = 0.f;
        if (jg1 < 16) hv = __ldcg(&g_h[b1o * HC + j1]);   // for r*h
        float pre2v = 0.f, hov = 0.f;
        if (p2own) {
            pre2v = __ldcg(&g_pre2[((size_t)t * B_DIM + b2o) * HC + j2]);
            hov   = __ldcg(&g_h[b2o * HC + j2]);
        }

        // ---- stage h[bg1*16 .. +16][:] as bf16 hi/lo (2048 float4) ----
        #pragma unroll
        for (int q = 0; q < 4; ++q) {
            int i4 = q * NT + tid;
            int row = i4 >> 7, c4 = i4 & 127;
            float4 v = __ldcg(&gh4[(size_t)bg1 * 2048 + i4]);
            uint2 hi, lo;
            split4(v, hi, lo);
            *(uint2*)&sHh[row * WS + c4 * 4] = hi;
            *(uint2*)&sHl[row * WS + c4 * 4] = lo;
        }
        __syncthreads();

        // ---- Phase 1 compute: h @ W1h^T on tensor cores ----
        {
            const int ks = wp >> 1;     // 0..7, k range [ks*64, +64)
            const int jp = wp & 1;      // j-tile pair
            float acc[2][4];
            #pragma unroll
            for (int jj = 0; jj < 2; ++jj)
                #pragma unroll
                for (int q = 0; q < 4; ++q) acc[jj][q] = 0.f;
            #pragma unroll
            for (int cc = 0; cc < 4; ++cc) {
                int kb = ks * 64 + cc * 16 + fkq;
                unsigned ah[4], al[4];
                ah[0] = *(const unsigned*)&sHh[frow * WS + kb];
                ah[1] = *(const unsigned*)&sHh[(frow + 8) * WS + kb];
                ah[2] = *(const unsigned*)&sHh[frow * WS + kb + 8];
                ah[3] = *(const unsigned*)&sHh[(frow + 8) * WS + kb + 8];
                al[0] = *(const unsigned*)&sHl[frow * WS + kb];
                al[1] = *(const unsigned*)&sHl[(frow + 8) * WS + kb];
                al[2] = *(const unsigned*)&sHl[frow * WS + kb + 8];
                al[3] = *(const unsigned*)&sHl[(frow + 8) * WS + kb + 8];
                #pragma unroll
                for (int jj = 0; jj < 2; ++jj) {
                    int jr = (jp * 2 + jj) * 8 + frow;
                    unsigned bh[2], bl_[2];
                    bh[0]  = *(const unsigned*)&sW1h[jr * WS + kb];
                    bh[1]  = *(const unsigned*)&sW1h[jr * WS + kb + 8];
                    bl_[0] = *(const unsigned*)&sW1l[jr * WS + kb];
                    bl_[1] = *(const unsigned*)&sW1l[jr * WS + kb + 8];
                    mma16816(acc[jj], ah, bh);
                    mma16816(acc[jj], ah, bl_);
                    mma16816(acc[jj], al, bh);
                }
            }
            #pragma unroll
            for (int jj = 0; jj < 2; ++jj)
                *(float4*)&red[((ks * 4 + jp * 2 + jj) * 32 + lane) * 4] =
                    *(float4*)acc[jj];
        }
        __syncthreads();

        // ---- Phase 1 epilogue: 1 output/thread (32j x 16b) ----
        {
            float s = 0.f;
            #pragma unroll
            for (int ks = 0; ks < 8; ++ks)
                s += red[((ks * 4 + jt1) * 32 + lf1) * 4 + cc1];
            float pre = s + pre1v;
            float sg  = __fdividef(1.f, 1.f + __expf(-pre));
            if (jg1 < 16) g_rh[b1o * HC + j1] = sg * hv;
            else          g_z[b1o * HC + (j1 - HC)] = sg;
        }
        grid_bar(++ep);

        // ---- stage rh[bg2*8 .. +8][:] into rows 0..7; prefetch z ----
        float zv = 0.f;
        if (p2own) zv = __ldcg(&g_z[b2o * HC + j2]);
        #pragma unroll
        for (int q = 0; q < 2; ++q) {
            int i4 = q * NT + tid;
            int row = i4 >> 7, c4 = i4 & 127;
            float4 v = __ldcg(&grh4[(size_t)bg2 * 1024 + i4]);
            uint2 hi, lo;
            split4(v, hi, lo);
            *(uint2*)&sHh[row * WS + c4 * 4] = hi;
            *(uint2*)&sHl[row * WS + c4 * 4] = lo;
        }
        __syncthreads();

        // ---- Phase 2 compute: rh @ W2h^T (rows 8..15 garbage, unused) ----
        {
            const int ks = wp >> 1;
            const int jp = wp & 1;
            float acc[2][4];
            #pragma unroll
            for (int jj = 0; jj < 2; ++jj)
                #pragma unroll
                for (int q = 0; q < 4; ++q) acc[jj][q] = 0.f;
            #pragma unroll
            for (int cc = 0; cc < 4; ++cc) {
                int kb = ks * 64 + cc * 16 + fkq;
                unsigned ah[4], al[4];
                ah[0] = *(const unsigned*)&sHh[frow * WS + kb];
                ah[1] = *(const unsigned*)&sHh[(frow + 8) * WS + kb];
                ah[2] = *(const unsigned*)&sHh[frow * WS + kb + 8];
                ah[3] = *(const unsigned*)&sHh[(frow + 8) * WS + kb + 8];
                al[0] = *(const unsigned*)&sHl[frow * WS + kb];
                al[1] = *(const unsigned*)&sHl[(frow + 8) * WS + kb];
                al[2] = *(const unsigned*)&sHl[frow * WS + kb + 8];
                al[3] = *(const unsigned*)&sHl[(frow + 8) * WS + kb + 8];
                #pragma unroll
                for (int jj = 0; jj < 2; ++jj) {
                    int jr = (jp * 2 + jj) * 8 + frow;
                    unsigned bh[2], bl_[2];
                    bh[0]  = *(const unsigned*)&sW2h[jr * WS + kb];
                    bh[1]  = *(const unsigned*)&sW2h[jr * WS + kb + 8];
                    bl_[0] = *(const unsigned*)&sW2l[jr * WS + kb];
                    bl_[1] = *(const unsigned*)&sW2l[jr * WS + kb + 8];
                    mma16816(acc[jj], ah, bh);
                    mma16816(acc[jj], ah, bl_);
                    mma16816(acc[jj], al, bh);
                }
            }
            #pragma unroll
            for (int jj = 0; jj < 2; ++jj)
                *(float4*)&red[((ks * 4 + jp * 2 + jj) * 32 + lane) * 4] =
                    *(float4*)acc[jj];
        }
        __syncthreads();

        // ---- Phase 2 epilogue: threads 0..255 (32j x 8b) ----
        if (p2own) {
            float s = 0.f;
            #pragma unroll
            for (int ks = 0; ks < 8; ++ks)
                s += red[((ks * 4 + jt2) * 32 + lf2) * 4 + cc2];
            float x2v = s + pre2v;
            float gg  = 1.f - __fdividef(2.f, __expf(2.f * x2v) + 1.f);
            float hn  = zv * hov + (1.f - zv) * gg;
            g_h[b2o * HC + j2] = hn;
            lout[((size_t)t * B_DIM + b2o) * HC + j2] = hn;
            if (t == T_DIM - 1)
                out[OUT_ACT + (size_t)l * B_DIM * HC + b2o * HC + j2] = hn;
        }
        grid_bar(++ep);
    }
}

extern "C" void kernel_launch(void* const* d_in, const int* in_sizes, int n_in,
                              void* d_out, int out_size) {
    const float* x       = (const float*)d_in[0];
    const float* hiddens = (const float*)d_in[1];
    const float* W1      = (const float*)d_in[2];
    const float* b1      = (const float*)d_in[3];
    const float* W2      = (const float*)d_in[4];
    const float* b2      = (const float*)d_in[5];
    float* out = (float*)d_out;

    cudaFuncSetAttribute(serial_kernel,
                         cudaFuncAttributeMaxDynamicSharedMemorySize,
                         SER_SMEM_BYTES);

    for (int l = 0; l < L_DIM; ++l) {
        conv_act<<<M_ALL * IC / 4 / 256, 256>>>(x, l);
        conv_w  <<<N_ALL * IC / 4 / 256, 256>>>(W1, W2, l);
        mma_hoist<<<dim3(24, M_ALL / MBM), 256>>>(b1, b2, l);
        serial_kernel<<<NB, NT, SER_SMEM_BYTES>>>(hiddens, W1, W2, out, l);
    }
}